// round 5
// baseline (speedup 1.0000x reference)
#include <cuda_runtime.h>
#include <math.h>

// Problem constants
#define Bb      8
#define Nn      2048
#define Cc      256
#define Ee      32768
#define Hh      8
#define CO      64
#define BN_TOT  (Bb * Nn)          // 16384 nodes
#define F       (Hh * CO)          // 512 features
#define BE      (Bb * Ee)          // 262144 real edges
#define ET      (BE + BN_TOT)      // 278528 edges incl. self loops
#define NEG     0.2f

// ---------------- scratch (static device globals; no allocation) ----------------
__device__ float g_xt[(size_t)BN_TOT * F];     // projected features, 32 MB
__device__ float g_asrc[BN_TOT * Hh];          // per-node src attention dot
__device__ float g_adst[BN_TOT * Hh];          // per-node dst attention dot
__device__ int   g_src[ET];
__device__ int   g_dst[ET];
__device__ int   g_cnt[BN_TOT];                // in-degree counts
__device__ int   g_rowptr[BN_TOT + 1];         // CSR row pointers (by dst)
__device__ int   g_ofs[BN_TOT];                // running offsets for place
__device__ int   g_csrc[ET];                   // CSR: src node per slot
__device__ int   g_is64;

// ---------------- detect edge dtype + zero counts (merged) ----------------------
__global__ void detect_zero_kernel(const unsigned* __restrict__ w) {
    int t = blockIdx.x * blockDim.x + threadIdx.x;
    if (t < BN_TOT) g_cnt[t] = 0;
    if (blockIdx.x == 0 && threadIdx.x < 32) {
        unsigned v = w[2 * threadIdx.x + 1];   // int64 => odd words zero
        unsigned all0 = __all_sync(0xffffffffu, v == 0u);
        if (threadIdx.x == 0) g_is64 = all0 ? 1 : 0;
    }
}

// ---------------- decode batched edges (+ self loops) and count in-degrees ------
__global__ void decode_count_kernel(const void* __restrict__ eiv) {
    int e = blockIdx.x * blockDim.x + threadIdx.x;
    if (e >= ET) return;
    int s, d;
    if (e < BE) {
        int k = e & (Ee - 1);
        int b = e >> 15;
        if (g_is64) {
            const long long* p = (const long long*)eiv;
            s = (int)p[k];
            d = (int)p[Ee + k];
        } else {
            const int* p = (const int*)eiv;
            s = p[k];
            d = p[Ee + k];
        }
        s += b * Nn;
        d += b * Nn;
    } else {
        s = d = e - BE;
    }
    g_src[e] = s;
    g_dst[e] = d;
    atomicAdd(&g_cnt[d], 1);
}

// ---------------- single-block exclusive scan over 16384 counts -----------------
__global__ void scan_kernel() {
    __shared__ int wsum[32];
    const int t = threadIdx.x;
    const int lane = t & 31;
    const int w = t >> 5;

    const int4* cin = (const int4*)g_cnt;
    int4 c0 = cin[t * 4 + 0];
    int4 c1 = cin[t * 4 + 1];
    int4 c2 = cin[t * 4 + 2];
    int4 c3 = cin[t * 4 + 3];
    int v[16] = {c0.x, c0.y, c0.z, c0.w, c1.x, c1.y, c1.z, c1.w,
                 c2.x, c2.y, c2.z, c2.w, c3.x, c3.y, c3.z, c3.w};

    int loc[16];
    int s = 0;
#pragma unroll
    for (int i = 0; i < 16; i++) { loc[i] = s; s += v[i]; }

    int inc = s;
#pragma unroll
    for (int o = 1; o < 32; o <<= 1) {
        int u = __shfl_up_sync(0xffffffffu, inc, o);
        if (lane >= o) inc += u;
    }
    if (lane == 31) wsum[w] = inc;
    __syncthreads();
    if (w == 0) {
        int x = wsum[lane];
#pragma unroll
        for (int o = 1; o < 32; o <<= 1) {
            int u = __shfl_up_sync(0xffffffffu, x, o);
            if (lane >= o) x += u;
        }
        wsum[lane] = x;
    }
    __syncthreads();

    int base_excl = (inc - s) + (w > 0 ? wsum[w - 1] : 0);

    int4* rp = (int4*)g_rowptr;
    int4* op = (int4*)g_ofs;
#pragma unroll
    for (int i = 0; i < 4; i++) {
        int4 q = make_int4(base_excl + loc[i * 4 + 0], base_excl + loc[i * 4 + 1],
                           base_excl + loc[i * 4 + 2], base_excl + loc[i * 4 + 3]);
        rp[t * 4 + i] = q;
        op[t * 4 + i] = q;
    }
    if (t == 1023) g_rowptr[BN_TOT] = wsum[31];
}

// ---------------- place edges into CSR slots ------------------------------------
__global__ void place_kernel() {
    int e = blockIdx.x * blockDim.x + threadIdx.x;
    if (e >= ET) return;
    int d = g_dst[e];
    int slot = atomicAdd(&g_ofs[d], 1);
    g_csrc[slot] = g_src[e];
}

// ---------------- 3xTF32 tensor-core GEMM ---------------------------------------
// xt[16384,512] = x[16384,256] @ W[256,512]
// 128x128 block tile, BK=16, 256 threads (8 warps, 4x2 warp grid),
// warp tile 32x64 via mma.sync.m16n8k8 tf32.
// A,B split into tf32-hi (cvt.rna) + fp32 residual; D = Ah*Bh + Ah*Bl + Al*Bh.
#define GBM 128
#define GBN 128
#define GBK 16
#define SPAD 4

__device__ __forceinline__ float tf32_hi(float x) {
    unsigned r;
    asm("cvt.rna.tf32.f32 %0, %1;" : "=r"(r) : "f"(x));
    return __uint_as_float(r);
}

#define MMA_TF32(d, a, b)                                                         \
    asm volatile("mma.sync.aligned.m16n8k8.row.col.f32.tf32.tf32.f32 "            \
                 "{%0,%1,%2,%3}, {%4,%5,%6,%7}, {%8,%9}, {%0,%1,%2,%3};"          \
                 : "+f"(d[0]), "+f"(d[1]), "+f"(d[2]), "+f"(d[3])                  \
                 : "r"(a[0]), "r"(a[1]), "r"(a[2]), "r"(a[3]), "r"(b[0]), "r"(b[1]))

__global__ void gemm_kernel(const float* __restrict__ A, const float* __restrict__ Bw) {
    __shared__ float Ah[GBK][GBM + SPAD], Al[GBK][GBM + SPAD];
    __shared__ float Bh[GBK][GBN + SPAD], Bl[GBK][GBN + SPAD];

    const int tid  = threadIdx.x;
    const int lane = tid & 31;
    const int wid  = tid >> 5;
    const int wr   = wid >> 1;       // 0..3 warp row
    const int wc   = wid & 1;        // 0..1 warp col
    const int bx   = blockIdx.x;     // N/128 = 4
    const int by   = blockIdx.y;     // M/128 = 128

    float acc[2][8][4];
#pragma unroll
    for (int i = 0; i < 2; i++)
#pragma unroll
        for (int j = 0; j < 8; j++)
#pragma unroll
            for (int k = 0; k < 4; k++) acc[i][j][k] = 0.0f;

    const int qr = lane >> 2;        // 0..7
    const int qc = lane & 3;         // 0..3

    for (int k0 = 0; k0 < Cc; k0 += GBK) {
#pragma unroll
        for (int i = 0; i < 2; i++) {
            int idx = tid + i * 256;            // 0..511
            int r = idx >> 2;                   // 0..127
            int c4 = (idx & 3) << 2;            // 0,4,8,12
            float4 v = *(const float4*)(A + (size_t)(by * GBM + r) * Cc + k0 + c4);
            float h0 = tf32_hi(v.x), h1 = tf32_hi(v.y), h2 = tf32_hi(v.z), h3 = tf32_hi(v.w);
            Ah[c4 + 0][r] = h0; Al[c4 + 0][r] = v.x - h0;
            Ah[c4 + 1][r] = h1; Al[c4 + 1][r] = v.y - h1;
            Ah[c4 + 2][r] = h2; Al[c4 + 2][r] = v.z - h2;
            Ah[c4 + 3][r] = h3; Al[c4 + 3][r] = v.w - h3;
        }
#pragma unroll
        for (int i = 0; i < 2; i++) {
            int idx = tid + i * 256;
            int r = idx >> 5;                   // 0..15
            int c4 = (idx & 31) << 2;           // 0..124
            float4 v = *(const float4*)(Bw + (size_t)(k0 + r) * F + bx * GBN + c4);
            float h0 = tf32_hi(v.x), h1 = tf32_hi(v.y), h2 = tf32_hi(v.z), h3 = tf32_hi(v.w);
            Bh[r][c4 + 0] = h0; Bl[r][c4 + 0] = v.x - h0;
            Bh[r][c4 + 1] = h1; Bl[r][c4 + 1] = v.y - h1;
            Bh[r][c4 + 2] = h2; Bl[r][c4 + 2] = v.z - h2;
            Bh[r][c4 + 3] = h3; Bl[r][c4 + 3] = v.w - h3;
        }
        __syncthreads();

#pragma unroll
        for (int kk = 0; kk < GBK; kk += 8) {
            unsigned ah[2][4], al[2][4];
            const int cA = kk + qc;
#pragma unroll
            for (int mt = 0; mt < 2; mt++) {
                int rm = wr * 32 + mt * 16 + qr;
                ah[mt][0] = __float_as_uint(Ah[cA][rm]);
                ah[mt][1] = __float_as_uint(Ah[cA][rm + 8]);
                ah[mt][2] = __float_as_uint(Ah[cA + 4][rm]);
                ah[mt][3] = __float_as_uint(Ah[cA + 4][rm + 8]);
                al[mt][0] = __float_as_uint(Al[cA][rm]);
                al[mt][1] = __float_as_uint(Al[cA][rm + 8]);
                al[mt][2] = __float_as_uint(Al[cA + 4][rm]);
                al[mt][3] = __float_as_uint(Al[cA + 4][rm + 8]);
            }
            unsigned bh[8][2], bl[8][2];
            const int kB = kk + qc;
#pragma unroll
            for (int nt = 0; nt < 8; nt++) {
                int nn = wc * 64 + nt * 8 + qr;
                bh[nt][0] = __float_as_uint(Bh[kB][nn]);
                bh[nt][1] = __float_as_uint(Bh[kB + 4][nn]);
                bl[nt][0] = __float_as_uint(Bl[kB][nn]);
                bl[nt][1] = __float_as_uint(Bl[kB + 4][nn]);
            }
#pragma unroll
            for (int mt = 0; mt < 2; mt++)
#pragma unroll
                for (int nt = 0; nt < 8; nt++) {
                    MMA_TF32(acc[mt][nt], ah[mt], bh[nt]);
                    MMA_TF32(acc[mt][nt], ah[mt], bl[nt]);
                    MMA_TF32(acc[mt][nt], al[mt], bh[nt]);
                }
        }
        __syncthreads();
    }

#pragma unroll
    for (int mt = 0; mt < 2; mt++) {
        int r = by * GBM + wr * 32 + mt * 16 + qr;
#pragma unroll
        for (int nt = 0; nt < 8; nt++) {
            int c = bx * GBN + wc * 64 + nt * 8 + qc * 2;
            *(float2*)&g_xt[(size_t)r * F + c]       = make_float2(acc[mt][nt][0], acc[mt][nt][1]);
            *(float2*)&g_xt[(size_t)(r + 8) * F + c] = make_float2(acc[mt][nt][2], acc[mt][nt][3]);
        }
    }
}

// ---------------- per-(node,head) attention dot products (warp each) ------------
__global__ void attdot_kernel(const float* __restrict__ att_src,
                              const float* __restrict__ att_dst) {
    int gw = (blockIdx.x * blockDim.x + threadIdx.x) >> 5;
    int lane = threadIdx.x & 31;
    if (gw >= BN_TOT * Hh) return;
    int n = gw >> 3, h = gw & 7;

    const float* row = g_xt + (size_t)n * F + h * CO;
    float2 v  = *(const float2*)&row[lane * 2];
    float2 as = *(const float2*)&att_src[h * CO + lane * 2];
    float2 ad = *(const float2*)&att_dst[h * CO + lane * 2];
    float s = v.x * as.x + v.y * as.y;
    float d = v.x * ad.x + v.y * ad.y;
#pragma unroll
    for (int o = 16; o; o >>= 1) {
        s += __shfl_xor_sync(0xffffffffu, s, o);
        d += __shfl_xor_sync(0xffffffffu, d, o);
    }
    if (lane == 0) { g_asrc[gw] = s; g_adst[gw] = d; }
}

// ---------------- fused softmax + weighted gather (no atomics) ------------------
// One block per dst node; one warp per head.
// Accumulation: 2 edges/iteration, 16 lanes x float4 per edge. All shuffles are
// warp-uniform (every lane executes the same j and j+1 shuffles each iteration);
// only the guarded load diverges. This is the fix for the R4 UB.
__global__ void gather_kernel(float* __restrict__ out, const float* __restrict__ bias) {
    int n = blockIdx.x;
    int h = threadIdx.x >> 5;
    int lane = threadIdx.x & 31;
    int start = g_rowptr[n];
    int end   = g_rowptr[n + 1];
    int deg   = end - start;

    float adstv = g_adst[n * Hh + h];
    int half = lane >> 4;                 // which of the 2 edges this lane handles
    int cl   = lane & 15;                 // channel lane (x4 floats)
    const float* xb = g_xt + h * CO + cl * 4;

    float4 acc = make_float4(0.f, 0.f, 0.f, 0.f);

    if (deg <= 32) {
        // fast path: one logit + one expf per edge-head, softmax fully in regs
        int s = 0;
        float l = -1e30f;
        if (lane < deg) {
            s = g_csrc[start + lane];
            float t = g_asrc[s * Hh + h] + adstv;
            l = (t > 0.0f) ? t : NEG * t;
        }
        float m = l;
#pragma unroll
        for (int o = 16; o; o >>= 1) m = fmaxf(m, __shfl_xor_sync(0xffffffffu, m, o));
        float wgt = (lane < deg) ? expf(l - m) : 0.0f;
        float sum = wgt;
#pragma unroll
        for (int o = 16; o; o >>= 1) sum += __shfl_xor_sync(0xffffffffu, sum, o);
        float a = wgt / (sum + 1e-16f);

        for (int j = 0; j < deg; j += 2) {
            float a0 = __shfl_sync(0xffffffffu, a, j);
            int   s0 = __shfl_sync(0xffffffffu, s, j);
            float a1 = __shfl_sync(0xffffffffu, a, j + 1);   // j+1 <= 31 always
            int   s1 = __shfl_sync(0xffffffffu, s, j + 1);
            float aj = half ? a1 : a0;
            int   sj = half ? s1 : s0;
            if (j + half < deg) {
                float4 v = *(const float4*)(xb + (size_t)sj * F);
                acc.x += aj * v.x; acc.y += aj * v.y;
                acc.z += aj * v.z; acc.w += aj * v.w;
            }
        }
    } else {
        // general path (rare): two reduction passes + chunked accumulation
        float m = -1e30f;
        for (int i = start + lane; i < end; i += 32) {
            int s = g_csrc[i];
            float t = g_asrc[s * Hh + h] + adstv;
            t = (t > 0.0f) ? t : NEG * t;
            m = fmaxf(m, t);
        }
#pragma unroll
        for (int o = 16; o; o >>= 1) m = fmaxf(m, __shfl_xor_sync(0xffffffffu, m, o));

        float sum = 0.0f;
        for (int i = start + lane; i < end; i += 32) {
            int s = g_csrc[i];
            float t = g_asrc[s * Hh + h] + adstv;
            t = (t > 0.0f) ? t : NEG * t;
            sum += expf(t - m);
        }
#pragma unroll
        for (int o = 16; o; o >>= 1) sum += __shfl_xor_sync(0xffffffffu, sum, o);
        float inv = 1.0f / (sum + 1e-16f);

        for (int base = start; base < end; base += 32) {
            int i = base + lane;
            int sreg = 0;
            float areg = 0.0f;
            if (i < end) {
                sreg = g_csrc[i];
                float t = g_asrc[sreg * Hh + h] + adstv;
                t = (t > 0.0f) ? t : NEG * t;
                areg = expf(t - m) * inv;
            }
            int cnt = end - base;
            if (cnt > 32) cnt = 32;
            for (int j = 0; j < cnt; j += 2) {
                float a0 = __shfl_sync(0xffffffffu, areg, j);
                int   s0 = __shfl_sync(0xffffffffu, sreg, j);
                float a1 = __shfl_sync(0xffffffffu, areg, j + 1);
                int   s1 = __shfl_sync(0xffffffffu, sreg, j + 1);
                float aj = half ? a1 : a0;
                int   sj = half ? s1 : s0;
                if (j + half < cnt) {
                    float4 v = *(const float4*)(xb + (size_t)sj * F);
                    acc.x += aj * v.x; acc.y += aj * v.y;
                    acc.z += aj * v.z; acc.w += aj * v.w;
                }
            }
        }
    }

    // combine the two edge-parity halves
    acc.x += __shfl_xor_sync(0xffffffffu, acc.x, 16);
    acc.y += __shfl_xor_sync(0xffffffffu, acc.y, 16);
    acc.z += __shfl_xor_sync(0xffffffffu, acc.z, 16);
    acc.w += __shfl_xor_sync(0xffffffffu, acc.w, 16);

    if (half == 0) {
        int c = h * CO + cl * 4;
        float4 bv = *(const float4*)(bias + c);
        *(float4*)(out + (size_t)n * F + c) =
            make_float4(acc.x + bv.x, acc.y + bv.y, acc.z + bv.z, acc.w + bv.w);
    }
}

// ---------------- launch (fork-join: CSR build || GEMM+attdot) ------------------
extern "C" void kernel_launch(void* const* d_in, const int* in_sizes, int n_in,
                              void* d_out, int out_size) {
    const float* x    = (const float*)d_in[0];
    const void*  ei   = d_in[1];
    const float* W    = (const float*)d_in[2];
    const float* asrc = (const float*)d_in[3];
    const float* adst = (const float*)d_in[4];
    const float* bias = (const float*)d_in[5];
    float* out = (float*)d_out;

    static cudaStream_t s2 = nullptr;
    static cudaEvent_t ev_fork = nullptr, ev_join = nullptr;
    if (s2 == nullptr) {
        cudaStreamCreateWithFlags(&s2, cudaStreamNonBlocking);
        cudaEventCreateWithFlags(&ev_fork, cudaEventDisableTiming);
        cudaEventCreateWithFlags(&ev_join, cudaEventDisableTiming);
    }

    cudaEventRecord(ev_fork, 0);
    cudaStreamWaitEvent(s2, ev_fork, 0);

    gemm_kernel<<<dim3(F / GBN, BN_TOT / GBM), 256, 0, s2>>>(x, W);
    attdot_kernel<<<(BN_TOT * Hh * 32 + 255) / 256, 256, 0, s2>>>(asrc, adst);
    cudaEventRecord(ev_join, s2);

    detect_zero_kernel<<<BN_TOT / 256, 256>>>((const unsigned*)ei);
    decode_count_kernel<<<(ET + 255) / 256, 256>>>(ei);
    scan_kernel<<<1, 1024>>>();
    place_kernel<<<(ET + 255) / 256, 256>>>();

    cudaStreamWaitEvent(0, ev_join, 0);
    gather_kernel<<<BN_TOT, 256>>>(out, bias);
}

// round 6
// speedup vs baseline: 1.1971x; 1.1971x over previous
#include <cuda_runtime.h>
#include <math.h>

// Problem constants
#define Bb      8
#define Nn      2048
#define Cc      256
#define Ee      32768
#define Hh      8
#define CO      64
#define BN_TOT  (Bb * Nn)          // 16384 nodes
#define F       (Hh * CO)          // 512 features
#define BE      (Bb * Ee)          // 262144 real edges
#define ET      (BE + BN_TOT)      // 278528 edges incl. self loops
#define NEG     0.2f

// ---------------- scratch (static device globals; no allocation) ----------------
__device__ float g_xt[(size_t)BN_TOT * F];     // projected features, 32 MB
__device__ float g_asrc[BN_TOT * Hh];          // per-node src attention dot
__device__ float g_adst[BN_TOT * Hh];          // per-node dst attention dot
__device__ int   g_src[ET];
__device__ int   g_dst[ET];
__device__ int   g_cnt[BN_TOT];                // in-degree counts
__device__ int   g_rowptr[BN_TOT + 1];         // CSR row pointers (by dst)
__device__ int   g_ofs[BN_TOT];                // running offsets for place
__device__ int   g_csrc[ET];                   // CSR: src node per slot
__device__ int   g_is64;

// ---------------- detect edge dtype + zero counts (merged) ----------------------
__global__ void detect_zero_kernel(const unsigned* __restrict__ w) {
    int t = blockIdx.x * blockDim.x + threadIdx.x;
    if (t < BN_TOT) g_cnt[t] = 0;
    if (blockIdx.x == 0 && threadIdx.x < 32) {
        unsigned v = w[2 * threadIdx.x + 1];   // int64 => odd words zero
        unsigned all0 = __all_sync(0xffffffffu, v == 0u);
        if (threadIdx.x == 0) g_is64 = all0 ? 1 : 0;
    }
}

// ---------------- decode batched edges (+ self loops) and count in-degrees ------
__global__ void decode_count_kernel(const void* __restrict__ eiv) {
    int e = blockIdx.x * blockDim.x + threadIdx.x;
    if (e >= ET) return;
    int s, d;
    if (e < BE) {
        int k = e & (Ee - 1);
        int b = e >> 15;
        if (g_is64) {
            const long long* p = (const long long*)eiv;
            s = (int)p[k];
            d = (int)p[Ee + k];
        } else {
            const int* p = (const int*)eiv;
            s = p[k];
            d = p[Ee + k];
        }
        s += b * Nn;
        d += b * Nn;
    } else {
        s = d = e - BE;
    }
    g_src[e] = s;
    g_dst[e] = d;
    atomicAdd(&g_cnt[d], 1);
}

// ---------------- single-block exclusive scan over 16384 counts -----------------
__global__ void scan_kernel() {
    __shared__ int wsum[32];
    const int t = threadIdx.x;
    const int lane = t & 31;
    const int w = t >> 5;

    const int4* cin = (const int4*)g_cnt;
    int4 c0 = cin[t * 4 + 0];
    int4 c1 = cin[t * 4 + 1];
    int4 c2 = cin[t * 4 + 2];
    int4 c3 = cin[t * 4 + 3];
    int v[16] = {c0.x, c0.y, c0.z, c0.w, c1.x, c1.y, c1.z, c1.w,
                 c2.x, c2.y, c2.z, c2.w, c3.x, c3.y, c3.z, c3.w};

    int loc[16];
    int s = 0;
#pragma unroll
    for (int i = 0; i < 16; i++) { loc[i] = s; s += v[i]; }

    int inc = s;
#pragma unroll
    for (int o = 1; o < 32; o <<= 1) {
        int u = __shfl_up_sync(0xffffffffu, inc, o);
        if (lane >= o) inc += u;
    }
    if (lane == 31) wsum[w] = inc;
    __syncthreads();
    if (w == 0) {
        int x = wsum[lane];
#pragma unroll
        for (int o = 1; o < 32; o <<= 1) {
            int u = __shfl_up_sync(0xffffffffu, x, o);
            if (lane >= o) x += u;
        }
        wsum[lane] = x;
    }
    __syncthreads();

    int base_excl = (inc - s) + (w > 0 ? wsum[w - 1] : 0);

    int4* rp = (int4*)g_rowptr;
    int4* op = (int4*)g_ofs;
#pragma unroll
    for (int i = 0; i < 4; i++) {
        int4 q = make_int4(base_excl + loc[i * 4 + 0], base_excl + loc[i * 4 + 1],
                           base_excl + loc[i * 4 + 2], base_excl + loc[i * 4 + 3]);
        rp[t * 4 + i] = q;
        op[t * 4 + i] = q;
    }
    if (t == 1023) g_rowptr[BN_TOT] = wsum[31];
}

// ---------------- place edges into CSR slots ------------------------------------
__global__ void place_kernel() {
    int e = blockIdx.x * blockDim.x + threadIdx.x;
    if (e >= ET) return;
    int d = g_dst[e];
    int slot = atomicAdd(&g_ofs[d], 1);
    g_csrc[slot] = g_src[e];
}

// ---------------- fp32 GEMM (128x128x16, 8x8 reg tile) + fused attdot -----------
// xt[16384,512] = x[16384,256] @ W[256,512], column-chunked by bx0 so gathers
// for finished head groups can overlap the remaining GEMM work.
// Epilogue also computes asrc/adst per (node, head) via 8-lane shfl reduction.
#define TM 128
#define TN 128
#define BK 16
__global__ void gemm_kernel(const float* __restrict__ A, const float* __restrict__ Bw,
                            const float* __restrict__ att_src,
                            const float* __restrict__ att_dst, int bx0) {
    __shared__ float As[BK][TM];
    __shared__ float Bs[BK][TN];

    const int tid = threadIdx.x;
    const int bx  = bx0 + blockIdx.x;       // column block (0..3)
    const int by  = blockIdx.y;             // row block (0..127)

    const int tr = (tid >> 4) << 3;          // 0..120 step 8
    const int tc = (tid & 15) << 3;          // 0..120 step 8

    const int ar = tid >> 2;                 // 0..63
    const int ak = (tid & 3) << 2;           // 0,4,8,12
    const int br = tid >> 5;                 // 0..7
    const int bc = (tid & 31) << 2;          // 0..124

    float acc[8][8] = {};

    const float* Ap = A + (size_t)(by * TM + ar) * Cc + ak;
    const float* Bp = Bw + (size_t)br * F + bx * TN + bc;

    for (int k0 = 0; k0 < Cc; k0 += BK) {
        float4 a0 = *(const float4*)(Ap + k0);
        float4 a1 = *(const float4*)(Ap + (size_t)64 * Cc + k0);
        As[ak + 0][ar] = a0.x; As[ak + 1][ar] = a0.y;
        As[ak + 2][ar] = a0.z; As[ak + 3][ar] = a0.w;
        As[ak + 0][ar + 64] = a1.x; As[ak + 1][ar + 64] = a1.y;
        As[ak + 2][ar + 64] = a1.z; As[ak + 3][ar + 64] = a1.w;
        *(float4*)&Bs[br][bc]     = *(const float4*)(Bp + (size_t)k0 * F);
        *(float4*)&Bs[br + 8][bc] = *(const float4*)(Bp + (size_t)(k0 + 8) * F);
        __syncthreads();

#pragma unroll
        for (int k = 0; k < BK; k++) {
            float4 x0 = *(const float4*)&As[k][tr];
            float4 x1 = *(const float4*)&As[k][tr + 4];
            float4 y0 = *(const float4*)&Bs[k][tc];
            float4 y1 = *(const float4*)&Bs[k][tc + 4];
            float av[8] = {x0.x, x0.y, x0.z, x0.w, x1.x, x1.y, x1.z, x1.w};
            float bv[8] = {y0.x, y0.y, y0.z, y0.w, y1.x, y1.y, y1.z, y1.w};
#pragma unroll
            for (int i = 0; i < 8; i++)
#pragma unroll
                for (int j = 0; j < 8; j++)
                    acc[i][j] += av[i] * bv[j];
        }
        __syncthreads();
    }

    // store xt tile
#pragma unroll
    for (int i = 0; i < 8; i++) {
        size_t row = (size_t)(by * TM + tr + i);
        float* o = g_xt + row * F + bx * TN + tc;
        *(float4*)(o)     = make_float4(acc[i][0], acc[i][1], acc[i][2], acc[i][3]);
        *(float4*)(o + 4) = make_float4(acc[i][4], acc[i][5], acc[i][6], acc[i][7]);
    }

    // fused attdot: this thread's 8 cols lie inside ONE head (tc mod 64 <= 56).
    // 8 lanes (tid&7 selecting 64 channels) reduce via shfl_xor 1,2,4.
    {
        const int lane = tid & 31;
        const int h    = bx * 2 + (tc >> 6);
        const int chb  = tc & 63;
        const float* asv = att_src + h * CO + chb;
        const float* adv = att_dst + h * CO + chb;
        float as[8], ad[8];
#pragma unroll
        for (int j = 0; j < 8; j++) { as[j] = asv[j]; ad[j] = adv[j]; }

#pragma unroll
        for (int i = 0; i < 8; i++) {
            float s = 0.0f, d = 0.0f;
#pragma unroll
            for (int j = 0; j < 8; j++) {
                s += acc[i][j] * as[j];
                d += acc[i][j] * ad[j];
            }
#pragma unroll
            for (int o = 1; o <= 4; o <<= 1) {
                s += __shfl_xor_sync(0xffffffffu, s, o);
                d += __shfl_xor_sync(0xffffffffu, d, o);
            }
            if ((lane & 7) == 0) {
                int n = by * TM + tr + i;
                g_asrc[n * Hh + h] = s;
                g_adst[n * Hh + h] = d;
            }
        }
    }
}

// ---------------- fused softmax + weighted gather for a 4-head group ------------
// One block per dst node (128 threads = 4 warps); warp w handles head hbase+w.
// Fast path (deg<=32): one logit + one expf per edge-head, alpha kept in regs.
// Accumulation loop is the R3-proven converged form: all 32 lanes iterate the
// same j, 2 shuffles + one coalesced 256B float2 load per edge.
__global__ void gather_kernel(float* __restrict__ out, const float* __restrict__ bias,
                              int hbase) {
    int n = blockIdx.x;
    int h = hbase + (threadIdx.x >> 5);
    int lane = threadIdx.x & 31;
    int start = g_rowptr[n];
    int end   = g_rowptr[n + 1];
    int deg   = end - start;

    float adstv = g_adst[n * Hh + h];
    const float* xb = g_xt + h * CO + lane * 2;

    float2 acc = make_float2(0.0f, 0.0f);

    if (deg <= 32) {
        int s = 0;
        float l = -1e30f;
        if (lane < deg) {
            s = g_csrc[start + lane];
            float t = g_asrc[s * Hh + h] + adstv;
            l = (t > 0.0f) ? t : NEG * t;
        }
        float m = l;
#pragma unroll
        for (int o = 16; o; o >>= 1) m = fmaxf(m, __shfl_xor_sync(0xffffffffu, m, o));
        float wgt = (lane < deg) ? expf(l - m) : 0.0f;
        float sum = wgt;
#pragma unroll
        for (int o = 16; o; o >>= 1) sum += __shfl_xor_sync(0xffffffffu, sum, o);
        float a = wgt / (sum + 1e-16f);

        for (int j = 0; j < deg; j++) {
            float aj = __shfl_sync(0xffffffffu, a, j);
            int   sj = __shfl_sync(0xffffffffu, s, j);
            float2 v = *(const float2*)(xb + (size_t)sj * F);
            acc.x += aj * v.x;
            acc.y += aj * v.y;
        }
    } else {
        // general path (rare)
        float m = -1e30f;
        for (int i = start + lane; i < end; i += 32) {
            int s = g_csrc[i];
            float t = g_asrc[s * Hh + h] + adstv;
            t = (t > 0.0f) ? t : NEG * t;
            m = fmaxf(m, t);
        }
#pragma unroll
        for (int o = 16; o; o >>= 1) m = fmaxf(m, __shfl_xor_sync(0xffffffffu, m, o));

        float sum = 0.0f;
        for (int i = start + lane; i < end; i += 32) {
            int s = g_csrc[i];
            float t = g_asrc[s * Hh + h] + adstv;
            t = (t > 0.0f) ? t : NEG * t;
            sum += expf(t - m);
        }
#pragma unroll
        for (int o = 16; o; o >>= 1) sum += __shfl_xor_sync(0xffffffffu, sum, o);
        float inv = 1.0f / (sum + 1e-16f);

        for (int base = start; base < end; base += 32) {
            int i = base + lane;
            int sreg = 0;
            float areg = 0.0f;
            if (i < end) {
                sreg = g_csrc[i];
                float t = g_asrc[sreg * Hh + h] + adstv;
                t = (t > 0.0f) ? t : NEG * t;
                areg = expf(t - m) * inv;
            }
            int cnt = end - base;
            if (cnt > 32) cnt = 32;
            for (int j = 0; j < cnt; j++) {
                float aj = __shfl_sync(0xffffffffu, areg, j);
                int   sj = __shfl_sync(0xffffffffu, sreg, j);
                float2 v = *(const float2*)(xb + (size_t)sj * F);
                acc.x += aj * v.x;
                acc.y += aj * v.y;
            }
        }
    }

    int c = h * CO + lane * 2;
    float2 bv = *(const float2*)(bias + c);
    *(float2*)(out + (size_t)n * F + c) = make_float2(acc.x + bv.x, acc.y + bv.y);
}

// ---------------- launch: CSR build || chunked GEMM, pipelined gathers ----------
extern "C" void kernel_launch(void* const* d_in, const int* in_sizes, int n_in,
                              void* d_out, int out_size) {
    const float* x    = (const float*)d_in[0];
    const void*  ei   = d_in[1];
    const float* W    = (const float*)d_in[2];
    const float* asrc = (const float*)d_in[3];
    const float* adst = (const float*)d_in[4];
    const float* bias = (const float*)d_in[5];
    float* out = (float*)d_out;

    static cudaStream_t s2 = nullptr;
    static cudaEvent_t ev_fork = nullptr, ev_g0 = nullptr, ev_g1 = nullptr;
    if (s2 == nullptr) {
        cudaStreamCreateWithFlags(&s2, cudaStreamNonBlocking);
        cudaEventCreateWithFlags(&ev_fork, cudaEventDisableTiming);
        cudaEventCreateWithFlags(&ev_g0, cudaEventDisableTiming);
        cudaEventCreateWithFlags(&ev_g1, cudaEventDisableTiming);
    }

    cudaEventRecord(ev_fork, 0);
    cudaStreamWaitEvent(s2, ev_fork, 0);

    // GEMM chunk 0: columns 0..255 = heads 0..3 (with fused attdot)
    gemm_kernel<<<dim3(2, BN_TOT / TM), 256, 0, s2>>>(x, W, asrc, adst, 0);
    cudaEventRecord(ev_g0, s2);
    // GEMM chunk 1: columns 256..511 = heads 4..7
    gemm_kernel<<<dim3(2, BN_TOT / TM), 256, 0, s2>>>(x, W, asrc, adst, 2);
    cudaEventRecord(ev_g1, s2);

    // CSR build on the capture stream (hidden under GEMM chunk 0)
    detect_zero_kernel<<<BN_TOT / 256, 256>>>((const unsigned*)ei);
    decode_count_kernel<<<(ET + 255) / 256, 256>>>(ei);
    scan_kernel<<<1, 1024>>>();
    place_kernel<<<(ET + 255) / 256, 256>>>();

    // gather heads 0..3 overlaps GEMM chunk 1
    cudaStreamWaitEvent(0, ev_g0, 0);
    gather_kernel<<<BN_TOT, 128>>>(out, bias, 0);
    cudaStreamWaitEvent(0, ev_g1, 0);
    gather_kernel<<<BN_TOT, 128>>>(out, bias, 4);
}

// round 7
// speedup vs baseline: 1.3190x; 1.1018x over previous
#include <cuda_runtime.h>
#include <cuda_fp16.h>
#include <math.h>

// Problem constants
#define Bb      8
#define Nn      2048
#define Cc      256
#define Ee      32768
#define Hh      8
#define CO      64
#define BN_TOT  (Bb * Nn)          // 16384 nodes
#define F       (Hh * CO)          // 512 features
#define BE      (Bb * Ee)          // 262144 real edges
#define ET      (BE + BN_TOT)      // 278528 edges incl. self loops
#define NEG     0.2f

// ---------------- scratch (static device globals; no allocation) ----------------
__device__ __half g_xt[(size_t)BN_TOT * F];    // projected features, fp16, 16 MB
__device__ float  g_asrc[BN_TOT * Hh];         // per-node src attention dot (fp32)
__device__ float  g_adst[BN_TOT * Hh];         // per-node dst attention dot (fp32)
__device__ int    g_src[ET];
__device__ int    g_dst[ET];
__device__ int    g_cnt[BN_TOT];               // in-degree counts
__device__ int    g_rowptr[BN_TOT + 1];        // CSR row pointers (by dst)
__device__ int    g_ofs[BN_TOT];               // running offsets for place
__device__ int    g_csrc[ET];                  // CSR: src node per slot
__device__ int    g_is64;

// ---------------- detect edge dtype + zero counts (merged) ----------------------
__global__ void detect_zero_kernel(const unsigned* __restrict__ w) {
    int t = blockIdx.x * blockDim.x + threadIdx.x;
    if (t < BN_TOT) g_cnt[t] = 0;
    if (blockIdx.x == 0 && threadIdx.x < 32) {
        unsigned v = w[2 * threadIdx.x + 1];   // int64 => odd words zero
        unsigned all0 = __all_sync(0xffffffffu, v == 0u);
        if (threadIdx.x == 0) g_is64 = all0 ? 1 : 0;
    }
}

// ---------------- decode batched edges (+ self loops) and count in-degrees ------
__global__ void decode_count_kernel(const void* __restrict__ eiv) {
    int e = blockIdx.x * blockDim.x + threadIdx.x;
    if (e >= ET) return;
    int s, d;
    if (e < BE) {
        int k = e & (Ee - 1);
        int b = e >> 15;
        if (g_is64) {
            const long long* p = (const long long*)eiv;
            s = (int)p[k];
            d = (int)p[Ee + k];
        } else {
            const int* p = (const int*)eiv;
            s = p[k];
            d = p[Ee + k];
        }
        s += b * Nn;
        d += b * Nn;
    } else {
        s = d = e - BE;
    }
    g_src[e] = s;
    g_dst[e] = d;
    atomicAdd(&g_cnt[d], 1);
}

// ---------------- single-block exclusive scan over 16384 counts -----------------
__global__ void scan_kernel() {
    __shared__ int wsum[32];
    const int t = threadIdx.x;
    const int lane = t & 31;
    const int w = t >> 5;

    const int4* cin = (const int4*)g_cnt;
    int4 c0 = cin[t * 4 + 0];
    int4 c1 = cin[t * 4 + 1];
    int4 c2 = cin[t * 4 + 2];
    int4 c3 = cin[t * 4 + 3];
    int v[16] = {c0.x, c0.y, c0.z, c0.w, c1.x, c1.y, c1.z, c1.w,
                 c2.x, c2.y, c2.z, c2.w, c3.x, c3.y, c3.z, c3.w};

    int loc[16];
    int s = 0;
#pragma unroll
    for (int i = 0; i < 16; i++) { loc[i] = s; s += v[i]; }

    int inc = s;
#pragma unroll
    for (int o = 1; o < 32; o <<= 1) {
        int u = __shfl_up_sync(0xffffffffu, inc, o);
        if (lane >= o) inc += u;
    }
    if (lane == 31) wsum[w] = inc;
    __syncthreads();
    if (w == 0) {
        int x = wsum[lane];
#pragma unroll
        for (int o = 1; o < 32; o <<= 1) {
            int u = __shfl_up_sync(0xffffffffu, x, o);
            if (lane >= o) x += u;
        }
        wsum[lane] = x;
    }
    __syncthreads();

    int base_excl = (inc - s) + (w > 0 ? wsum[w - 1] : 0);

    int4* rp = (int4*)g_rowptr;
    int4* op = (int4*)g_ofs;
#pragma unroll
    for (int i = 0; i < 4; i++) {
        int4 q = make_int4(base_excl + loc[i * 4 + 0], base_excl + loc[i * 4 + 1],
                           base_excl + loc[i * 4 + 2], base_excl + loc[i * 4 + 3]);
        rp[t * 4 + i] = q;
        op[t * 4 + i] = q;
    }
    if (t == 1023) g_rowptr[BN_TOT] = wsum[31];
}

// ---------------- place edges into CSR slots ------------------------------------
__global__ void place_kernel() {
    int e = blockIdx.x * blockDim.x + threadIdx.x;
    if (e >= ET) return;
    int d = g_dst[e];
    int slot = atomicAdd(&g_ofs[d], 1);
    g_csrc[slot] = g_src[e];
}

// ---------------- fp32 GEMM (128x128x16, 8x8 reg tile) + fused attdot -----------
// xt[16384,512] = x[16384,256] @ W[256,512], column-chunked by bx0.
// Epilogue: fp16 store of xt + asrc/adst per (node, head) from fp32 accumulators.
#define TM 128
#define TN 128
#define BK 16
__global__ void gemm_kernel(const float* __restrict__ A, const float* __restrict__ Bw,
                            const float* __restrict__ att_src,
                            const float* __restrict__ att_dst, int bx0) {
    __shared__ float As[BK][TM];
    __shared__ float Bs[BK][TN];

    const int tid = threadIdx.x;
    const int bx  = bx0 + blockIdx.x;       // column block (0..3)
    const int by  = blockIdx.y;             // row block (0..127)

    const int tr = (tid >> 4) << 3;          // 0..120 step 8
    const int tc = (tid & 15) << 3;          // 0..120 step 8

    const int ar = tid >> 2;                 // 0..63
    const int ak = (tid & 3) << 2;           // 0,4,8,12
    const int br = tid >> 5;                 // 0..7
    const int bc = (tid & 31) << 2;          // 0..124

    float acc[8][8] = {};

    const float* Ap = A + (size_t)(by * TM + ar) * Cc + ak;
    const float* Bp = Bw + (size_t)br * F + bx * TN + bc;

    for (int k0 = 0; k0 < Cc; k0 += BK) {
        float4 a0 = *(const float4*)(Ap + k0);
        float4 a1 = *(const float4*)(Ap + (size_t)64 * Cc + k0);
        As[ak + 0][ar] = a0.x; As[ak + 1][ar] = a0.y;
        As[ak + 2][ar] = a0.z; As[ak + 3][ar] = a0.w;
        As[ak + 0][ar + 64] = a1.x; As[ak + 1][ar + 64] = a1.y;
        As[ak + 2][ar + 64] = a1.z; As[ak + 3][ar + 64] = a1.w;
        *(float4*)&Bs[br][bc]     = *(const float4*)(Bp + (size_t)k0 * F);
        *(float4*)&Bs[br + 8][bc] = *(const float4*)(Bp + (size_t)(k0 + 8) * F);
        __syncthreads();

#pragma unroll
        for (int k = 0; k < BK; k++) {
            float4 x0 = *(const float4*)&As[k][tr];
            float4 x1 = *(const float4*)&As[k][tr + 4];
            float4 y0 = *(const float4*)&Bs[k][tc];
            float4 y1 = *(const float4*)&Bs[k][tc + 4];
            float av[8] = {x0.x, x0.y, x0.z, x0.w, x1.x, x1.y, x1.z, x1.w};
            float bv[8] = {y0.x, y0.y, y0.z, y0.w, y1.x, y1.y, y1.z, y1.w};
#pragma unroll
            for (int i = 0; i < 8; i++)
#pragma unroll
                for (int j = 0; j < 8; j++)
                    acc[i][j] += av[i] * bv[j];
        }
        __syncthreads();
    }

    // store xt tile as fp16 (8 halves = 16B per row)
#pragma unroll
    for (int i = 0; i < 8; i++) {
        size_t row = (size_t)(by * TM + tr + i);
        __half2 h4[4];
        h4[0] = __floats2half2_rn(acc[i][0], acc[i][1]);
        h4[1] = __floats2half2_rn(acc[i][2], acc[i][3]);
        h4[2] = __floats2half2_rn(acc[i][4], acc[i][5]);
        h4[3] = __floats2half2_rn(acc[i][6], acc[i][7]);
        *(uint4*)(g_xt + row * F + bx * TN + tc) = *(uint4*)h4;
    }

    // fused attdot (fp32 accumulators): this thread's 8 cols lie inside ONE head.
    {
        const int lane = tid & 31;
        const int h    = bx * 2 + (tc >> 6);
        const int chb  = tc & 63;
        const float* asv = att_src + h * CO + chb;
        const float* adv = att_dst + h * CO + chb;
        float as[8], ad[8];
#pragma unroll
        for (int j = 0; j < 8; j++) { as[j] = asv[j]; ad[j] = adv[j]; }

#pragma unroll
        for (int i = 0; i < 8; i++) {
            float s = 0.0f, d = 0.0f;
#pragma unroll
            for (int j = 0; j < 8; j++) {
                s += acc[i][j] * as[j];
                d += acc[i][j] * ad[j];
            }
#pragma unroll
            for (int o = 1; o <= 4; o <<= 1) {
                s += __shfl_xor_sync(0xffffffffu, s, o);
                d += __shfl_xor_sync(0xffffffffu, d, o);
            }
            if ((lane & 7) == 0) {
                int n = by * TM + tr + i;
                g_asrc[n * Hh + h] = s;
                g_adst[n * Hh + h] = d;
            }
        }
    }
}

// ---------------- fused softmax + weighted gather for a 4-head group ------------
// One block per dst node (128 threads = 4 warps); warp w handles head hbase+w.
// Features are fp16: one coalesced 128B half2 transaction per warp-edge.
__global__ void gather_kernel(float* __restrict__ out, const float* __restrict__ bias,
                              int hbase) {
    int n = blockIdx.x;
    int h = hbase + (threadIdx.x >> 5);
    int lane = threadIdx.x & 31;
    int start = g_rowptr[n];
    int end   = g_rowptr[n + 1];
    int deg   = end - start;

    float adstv = g_adst[n * Hh + h];
    const __half* xb = g_xt + h * CO + lane * 2;

    float2 acc = make_float2(0.0f, 0.0f);

    if (deg <= 32) {
        // fast path: one logit + one expf per edge-head, alpha kept in regs
        int s = 0;
        float l = -1e30f;
        if (lane < deg) {
            s = g_csrc[start + lane];
            float t = g_asrc[s * Hh + h] + adstv;
            l = (t > 0.0f) ? t : NEG * t;
        }
        float m = l;
#pragma unroll
        for (int o = 16; o; o >>= 1) m = fmaxf(m, __shfl_xor_sync(0xffffffffu, m, o));
        float wgt = (lane < deg) ? expf(l - m) : 0.0f;
        float sum = wgt;
#pragma unroll
        for (int o = 16; o; o >>= 1) sum += __shfl_xor_sync(0xffffffffu, sum, o);
        float a = wgt / (sum + 1e-16f);

        for (int j = 0; j < deg; j++) {
            float aj = __shfl_sync(0xffffffffu, a, j);
            int   sj = __shfl_sync(0xffffffffu, s, j);
            float2 v = __half22float2(*(const __half2*)(xb + (size_t)sj * F));
            acc.x += aj * v.x;
            acc.y += aj * v.y;
        }
    } else {
        // general path (rare)
        float m = -1e30f;
        for (int i = start + lane; i < end; i += 32) {
            int s = g_csrc[i];
            float t = g_asrc[s * Hh + h] + adstv;
            t = (t > 0.0f) ? t : NEG * t;
            m = fmaxf(m, t);
        }
#pragma unroll
        for (int o = 16; o; o >>= 1) m = fmaxf(m, __shfl_xor_sync(0xffffffffu, m, o));

        float sum = 0.0f;
        for (int i = start + lane; i < end; i += 32) {
            int s = g_csrc[i];
            float t = g_asrc[s * Hh + h] + adstv;
            t = (t > 0.0f) ? t : NEG * t;
            sum += expf(t - m);
        }
#pragma unroll
        for (int o = 16; o; o >>= 1) sum += __shfl_xor_sync(0xffffffffu, sum, o);
        float inv = 1.0f / (sum + 1e-16f);

        for (int base = start; base < end; base += 32) {
            int i = base + lane;
            int sreg = 0;
            float areg = 0.0f;
            if (i < end) {
                sreg = g_csrc[i];
                float t = g_asrc[sreg * Hh + h] + adstv;
                t = (t > 0.0f) ? t : NEG * t;
                areg = expf(t - m) * inv;
            }
            int cnt = end - base;
            if (cnt > 32) cnt = 32;
            for (int j = 0; j < cnt; j++) {
                float aj = __shfl_sync(0xffffffffu, areg, j);
                int   sj = __shfl_sync(0xffffffffu, sreg, j);
                float2 v = __half22float2(*(const __half2*)(xb + (size_t)sj * F));
                acc.x += aj * v.x;
                acc.y += aj * v.y;
            }
        }
    }

    int c = h * CO + lane * 2;
    float2 bv = *(const float2*)(bias + c);
    *(float2*)(out + (size_t)n * F + c) = make_float2(acc.x + bv.x, acc.y + bv.y);
}

// ---------------- launch: CSR build || chunked GEMM, pipelined gathers ----------
extern "C" void kernel_launch(void* const* d_in, const int* in_sizes, int n_in,
                              void* d_out, int out_size) {
    const float* x    = (const float*)d_in[0];
    const void*  ei   = d_in[1];
    const float* W    = (const float*)d_in[2];
    const float* asrc = (const float*)d_in[3];
    const float* adst = (const float*)d_in[4];
    const float* bias = (const float*)d_in[5];
    float* out = (float*)d_out;

    static cudaStream_t s2 = nullptr;
    static cudaEvent_t ev_fork = nullptr, ev_g0 = nullptr, ev_g1 = nullptr;
    if (s2 == nullptr) {
        cudaStreamCreateWithFlags(&s2, cudaStreamNonBlocking);
        cudaEventCreateWithFlags(&ev_fork, cudaEventDisableTiming);
        cudaEventCreateWithFlags(&ev_g0, cudaEventDisableTiming);
        cudaEventCreateWithFlags(&ev_g1, cudaEventDisableTiming);
    }

    cudaEventRecord(ev_fork, 0);
    cudaStreamWaitEvent(s2, ev_fork, 0);

    // GEMM chunk 0: columns 0..255 = heads 0..3 (with fused attdot)
    gemm_kernel<<<dim3(2, BN_TOT / TM), 256, 0, s2>>>(x, W, asrc, adst, 0);
    cudaEventRecord(ev_g0, s2);
    // GEMM chunk 1: columns 256..511 = heads 4..7
    gemm_kernel<<<dim3(2, BN_TOT / TM), 256, 0, s2>>>(x, W, asrc, adst, 2);
    cudaEventRecord(ev_g1, s2);

    // CSR build on the capture stream (hidden under GEMM chunk 0)
    detect_zero_kernel<<<BN_TOT / 256, 256>>>((const unsigned*)ei);
    decode_count_kernel<<<(ET + 255) / 256, 256>>>(ei);
    scan_kernel<<<1, 1024>>>();
    place_kernel<<<(ET + 255) / 256, 256>>>();

    // gather heads 0..3 overlaps GEMM chunk 1
    cudaStreamWaitEvent(0, ev_g0, 0);
    gather_kernel<<<BN_TOT, 128>>>(out, bias, 0);
    cudaStreamWaitEvent(0, ev_g1, 0);
    gather_kernel<<<BN_TOT, 128>>>(out, bias, 4);
}